// round 5
// baseline (speedup 1.0000x reference)
#include <cuda_runtime.h>
#include <math.h>
#include <stdint.h>

#define N_NODES 100000
#define N_EDGES 1600000
#define HID 128
#define EPS 1e-5f

// ---------------- scratch (device globals; referenced ONLY in device code) ----------------
__device__ float  d_h0[N_NODES * HID];
__device__ float  d_h1[N_NODES * HID];
__device__ float  d_g [N_NODES * HID];   // dinv-scaled h@W ; head reuses as ff[N,32]
__device__ float  d_agg[N_NODES * HID];
__device__ float  d_dinv[N_NODES];
__device__ int    d_cnt[N_NODES];
__device__ int    d_cursor[N_NODES];
__device__ int    d_rowptr[N_NODES + 1];
__device__ int    d_col[N_EDGES];
__device__ int    d_bsums[128];
__device__ double d_bnSum[HID];
__device__ double d_bnSqs[HID];
__device__ float  d_bnA[HID];
__device__ float  d_bnC[HID];
// k-pair-interleaved W images: Wp[L][p*128 + j] = pack{W[2p][j], W[2p+1][j]}
__device__ unsigned long long d_Wp[3][64 * 128];

// ---------------- f32x2 helpers ----------------
__device__ __forceinline__ void ffma2(unsigned long long& a, unsigned long long s,
                                      unsigned long long w) {
    asm("fma.rn.f32x2 %0, %1, %2, %0;" : "+l"(a) : "l"(s), "l"(w));
}
__device__ __forceinline__ float unpack_sum(unsigned long long a) {
    float lo, hi;
    asm("mov.b64 {%0, %1}, %2;" : "=f"(lo), "=f"(hi) : "l"(a));
    return lo + hi;
}
__device__ __forceinline__ unsigned long long packf2(float lo, float hi) {
    unsigned long long u;
    asm("mov.b64 %0, {%1, %2};" : "=l"(u) : "f"(lo), "f"(hi));
    return u;
}

// ---------------- generic helpers ----------------
__device__ __forceinline__ void add4(float4& a, const float4& v) {
    a.x += v.x; a.y += v.y; a.z += v.z; a.w += v.w;
}
__device__ __forceinline__ float* hbuf(int sel) { return sel == 0 ? d_h0 : d_h1; }

// ---------------- setup kernels ----------------
__global__ void k_zero_counts() {
    int i = blockIdx.x * blockDim.x + threadIdx.x;
    if (i < N_NODES) { d_cnt[i] = 0; d_cursor[i] = 0; }
}
__global__ void k_zero_bn() {
    int t = threadIdx.x;
    if (t < HID) { d_bnSum[t] = 0.0; d_bnSqs[t] = 0.0; }
}
__global__ void k_count(const int* __restrict__ ei) {
    int e = blockIdx.x * blockDim.x + threadIdx.x;
    if (e < N_EDGES) atomicAdd(&d_cnt[ei[N_EDGES + e]], 1);
}
__global__ void k_dinv() {
    int i = blockIdx.x * blockDim.x + threadIdx.x;
    if (i < N_NODES) d_dinv[i] = rsqrtf((float)d_cnt[i] + 1.0f);
}
__global__ void k_scan_local() {
    __shared__ int s[1024];
    int tid = threadIdx.x;
    int idx = blockIdx.x * 1024 + tid;
    int v = (idx < N_NODES) ? d_cnt[idx] : 0;
    s[tid] = v;
    __syncthreads();
    for (int off = 1; off < 1024; off <<= 1) {
        int t = (tid >= off) ? s[tid - off] : 0;
        __syncthreads();
        s[tid] += t;
        __syncthreads();
    }
    if (idx < N_NODES) d_rowptr[idx] = s[tid] - v;   // exclusive
    if (tid == 1023) d_bsums[blockIdx.x] = s[1023];
}
__global__ void k_scan_bsums(int nb) {
    __shared__ int sb[128];
    int t = threadIdx.x;
    sb[t] = (t < nb) ? d_bsums[t] : 0;
    __syncthreads();
    if (t == 0) {
        int run = 0;
        for (int i = 0; i < nb; i++) { int x = sb[i]; sb[i] = run; run += x; }
        d_rowptr[N_NODES] = run;
    }
    __syncthreads();
    if (t < nb) d_bsums[t] = sb[t];
}
__global__ void k_scan_add() {
    int idx = blockIdx.x * 1024 + threadIdx.x;
    if (idx < N_NODES) d_rowptr[idx] += d_bsums[blockIdx.x];
}
__global__ void k_fill(const int* __restrict__ ei) {
    int e = blockIdx.x * blockDim.x + threadIdx.x;
    if (e < N_EDGES) {
        int s = ei[e];
        int d = ei[N_EDGES + e];
        int pos = d_rowptr[d] + atomicAdd(&d_cursor[d], 1);
        d_col[pos] = s;
    }
}

// ---------------- W prep: k-pair interleave, 3 layers ----------------
__global__ void k_prep_w(const float* __restrict__ W1,
                         const float* __restrict__ W2,
                         const float* __restrict__ W3) {
    int idx = blockIdx.x * blockDim.x + threadIdx.x;
    if (idx >= 3 * 64 * 128) return;
    int L = idx / 8192;
    int r = idx & 8191;
    int p = r >> 7, j = r & 127;
    const float* W = (L == 0) ? W1 : (L == 1) ? W2 : W3;
    d_Wp[L][p * 128 + j] = packf2(W[(2 * p) * 128 + j], W[(2 * p + 1) * 128 + j]);
}

// ---------------- encoder: h0 = relu(x @ We + be) ----------------
__global__ void k_encoder(const float* __restrict__ x,
                          const float* __restrict__ We,
                          const float* __restrict__ be) {
    int gt = blockIdx.x * blockDim.x + threadIdx.x;
    if (gt >= N_NODES * 32) return;
    int i = gt >> 5, l = gt & 31;
    float x0 = __ldg(&x[2 * i]), x1 = __ldg(&x[2 * i + 1]);
    float4 w0 = __ldg(&((const float4*)We)[l]);
    float4 w1 = __ldg(&((const float4*)We)[32 + l]);
    float4 b  = __ldg(&((const float4*)be)[l]);
    float4 h;
    h.x = fmaxf(fmaf(x0, w0.x, fmaf(x1, w1.x, b.x)), 0.f);
    h.y = fmaxf(fmaf(x0, w0.y, fmaf(x1, w1.y, b.y)), 0.f);
    h.z = fmaxf(fmaf(x0, w0.z, fmaf(x1, w1.z, b.z)), 0.f);
    h.w = fmaxf(fmaf(x0, w0.w, fmaf(x1, w1.w, b.w)), 0.f);
    ((float4*)d_h0)[gt] = h;
}

// ---------------- d_g = dinv[i] * (h[sel] @ W_layer), FFMA2 GEMM ----------------
// warp computes 4 nodes x 128 outputs. k packed in pairs:
//   acc.lo += h[2p]*W[2p][j],  acc.hi += h[2p+1]*W[2p+1][j],  out[j] = lo+hi.
// h pairs come from SMEM via LDS.64 broadcast; W from the pre-interleaved u64 image.
__global__ void __launch_bounds__(256) k_gemm128(int layer, int hin_sel) {
    __shared__ __align__(16) float sH[8][4 * HID];   // per-warp: 4 node rows
    const int lane = threadIdx.x & 31;
    const int warp = threadIdx.x >> 5;
    const int gwid = (blockIdx.x * blockDim.x + threadIdx.x) >> 5;
    const int nwarps = (gridDim.x * blockDim.x) >> 5;
    const float4* H4 = reinterpret_cast<const float4*>(hbuf(hin_sel));
    const ulonglong2* Wp2 = reinterpret_cast<const ulonglong2*>(&d_Wp[layer][0]);
    float4* O4 = reinterpret_cast<float4*>(d_g);
    const unsigned long long* hp =
        reinterpret_cast<const unsigned long long*>(&sH[warp][0]);

    for (int base = gwid * 4; base < N_NODES; base += nwarps * 4) {
        // stage 4 rows into this warp's smem slice
        #pragma unroll
        for (int n = 0; n < 4; n++)
            ((float4*)&sH[warp][n * HID])[lane] = H4[(size_t)(base + n) * 32 + lane];
        __syncwarp();

        unsigned long long a[4][4];
        #pragma unroll
        for (int n = 0; n < 4; n++)
            #pragma unroll
            for (int m = 0; m < 4; m++) a[n][m] = 0ULL;

        #pragma unroll 4
        for (int p = 0; p < 64; p++) {
            ulonglong2 w01 = __ldg(&Wp2[p * 64 + 2 * lane]);
            ulonglong2 w23 = __ldg(&Wp2[p * 64 + 2 * lane + 1]);
            #pragma unroll
            for (int n = 0; n < 4; n++) {
                unsigned long long s = hp[n * 64 + p];
                ffma2(a[n][0], s, w01.x);
                ffma2(a[n][1], s, w01.y);
                ffma2(a[n][2], s, w23.x);
                ffma2(a[n][3], s, w23.y);
            }
        }
        __syncwarp();   // protect smem slice before next tile's stores

        #pragma unroll
        for (int n = 0; n < 4; n++) {
            float dv = d_dinv[base + n];
            float4 o;
            o.x = unpack_sum(a[n][0]) * dv;
            o.y = unpack_sum(a[n][1]) * dv;
            o.z = unpack_sum(a[n][2]) * dv;
            o.w = unpack_sum(a[n][3]) * dv;
            O4[(size_t)(base + n) * 32 + lane] = o;
        }
    }
}

// ---------------- aggregation: agg[i] = dinv[i]*(sum_in g[src] + g[i]); BN partials ---
__global__ void k_aggregate() {
    __shared__ float sS[HID];
    __shared__ float sQ[HID];
    if (threadIdx.x < HID) { sS[threadIdx.x] = 0.f; sQ[threadIdx.x] = 0.f; }
    __syncthreads();

    const int lane = threadIdx.x & 31;
    const int gwid = (blockIdx.x * blockDim.x + threadIdx.x) >> 5;
    const int nwarps = (gridDim.x * blockDim.x) >> 5;
    const float4* g4 = reinterpret_cast<const float4*>(d_g);
    float4* agg4 = reinterpret_cast<float4*>(d_agg);

    float4 lsum = make_float4(0.f, 0.f, 0.f, 0.f);
    float4 lsq  = make_float4(0.f, 0.f, 0.f, 0.f);

    for (int i = gwid; i < N_NODES; i += nwarps) {
        float4 acc = g4[(size_t)i * 32 + lane];   // self loop
        int e0 = d_rowptr[i], e1 = d_rowptr[i + 1];
        for (int e = e0; e < e1; e++) {
            int s = __ldg(&d_col[e]);
            float4 v = __ldg(&g4[(size_t)s * 32 + lane]);
            add4(acc, v);
        }
        float dv = d_dinv[i];
        acc.x *= dv; acc.y *= dv; acc.z *= dv; acc.w *= dv;
        agg4[(size_t)i * 32 + lane] = acc;
        add4(lsum, acc);
        lsq.x = fmaf(acc.x, acc.x, lsq.x);
        lsq.y = fmaf(acc.y, acc.y, lsq.y);
        lsq.z = fmaf(acc.z, acc.z, lsq.z);
        lsq.w = fmaf(acc.w, acc.w, lsq.w);
    }
    int f = 4 * lane;
    atomicAdd(&sS[f + 0], lsum.x); atomicAdd(&sS[f + 1], lsum.y);
    atomicAdd(&sS[f + 2], lsum.z); atomicAdd(&sS[f + 3], lsum.w);
    atomicAdd(&sQ[f + 0], lsq.x);  atomicAdd(&sQ[f + 1], lsq.y);
    atomicAdd(&sQ[f + 2], lsq.z);  atomicAdd(&sQ[f + 3], lsq.w);
    __syncthreads();
    if (threadIdx.x < HID) {
        atomicAdd(&d_bnSum[threadIdx.x], (double)sS[threadIdx.x]);
        atomicAdd(&d_bnSqs[threadIdx.x], (double)sQ[threadIdx.x]);
    }
}

// ---------------- BN coeffs: a = gamma*rsqrt(var+eps), c = beta - mean*a ----------------
__global__ void k_bn_finalize(const float* __restrict__ gamma,
                              const float* __restrict__ beta, int nfeat) {
    int t = threadIdx.x;
    if (t < nfeat) {
        double mean = d_bnSum[t] / (double)N_NODES;
        double var  = d_bnSqs[t] / (double)N_NODES - mean * mean;
        float a = gamma[t] * rsqrtf((float)var + EPS);
        d_bnA[t] = a;
        d_bnC[t] = beta[t] - (float)mean * a;
    }
}

// ---------------- h[hout] = relu(a*agg + c) + h[hin] ----------------
__global__ void k_bnrelu_res(int hin_sel, int hout_sel) {
    int gt = blockIdx.x * blockDim.x + threadIdx.x;
    if (gt >= N_NODES * 32) return;
    int l = gt & 31;
    float4 a = ((const float4*)d_bnA)[l];
    float4 c = ((const float4*)d_bnC)[l];
    float4 v = ((const float4*)d_agg)[gt];
    float4 h = ((const float4*)hbuf(hin_sel))[gt];
    float4 r;
    r.x = fmaxf(fmaf(a.x, v.x, c.x), 0.f) + h.x;
    r.y = fmaxf(fmaf(a.y, v.y, c.y), 0.f) + h.y;
    r.z = fmaxf(fmaf(a.z, v.z, c.z), 0.f) + h.z;
    r.w = fmaxf(fmaf(a.w, v.w, c.w), 0.f) + h.w;
    ((float4*)hbuf(hout_sel))[gt] = r;
}

// ---------------- ff = h[sel] @ Wf1  (128 -> 32), stored in d_g ----------------
__global__ void k_gemm32(const float* __restrict__ W, int hin_sel) {
    __shared__ float sW[HID * 32];
    for (int i = threadIdx.x; i < HID * 32; i += blockDim.x) sW[i] = W[i];
    __syncthreads();
    const int lane = threadIdx.x & 31;
    const int gwid = (blockIdx.x * blockDim.x + threadIdx.x) >> 5;
    const int nwarps = (gridDim.x * blockDim.x) >> 5;
    const float4* H4 = reinterpret_cast<const float4*>(hbuf(hin_sel));
    for (int i = gwid; i < N_NODES; i += nwarps) {
        float4 h = H4[(size_t)i * 32 + lane];
        float acc = 0.f;
        #pragma unroll 8
        for (int q = 0; q < 32; q++) {
            float sx = __shfl_sync(0xffffffffu, h.x, q);
            float sy = __shfl_sync(0xffffffffu, h.y, q);
            float sz = __shfl_sync(0xffffffffu, h.z, q);
            float sw = __shfl_sync(0xffffffffu, h.w, q);
            acc = fmaf(sx, sW[(4 * q + 0) * 32 + lane], acc);
            acc = fmaf(sy, sW[(4 * q + 1) * 32 + lane], acc);
            acc = fmaf(sz, sW[(4 * q + 2) * 32 + lane], acc);
            acc = fmaf(sw, sW[(4 * q + 3) * 32 + lane], acc);
        }
        d_g[(size_t)i * 32 + lane] = acc;
    }
}

// ---------------- BN stats over ff[N,32] (in d_g) ----------------
__global__ void k_bnstats32() {
    __shared__ float sS[32];
    __shared__ float sQ[32];
    if (threadIdx.x < 32) { sS[threadIdx.x] = 0.f; sQ[threadIdx.x] = 0.f; }
    __syncthreads();
    const int lane = threadIdx.x & 31;
    const int gwid = (blockIdx.x * blockDim.x + threadIdx.x) >> 5;
    const int nwarps = (gridDim.x * blockDim.x) >> 5;
    float s = 0.f, q = 0.f;
    for (int i = gwid; i < N_NODES; i += nwarps) {
        float v = d_g[(size_t)i * 32 + lane];
        s += v;
        q = fmaf(v, v, q);
    }
    atomicAdd(&sS[lane], s);
    atomicAdd(&sQ[lane], q);
    __syncthreads();
    if (threadIdx.x < 32) {
        atomicAdd(&d_bnSum[threadIdx.x], (double)sS[threadIdx.x]);
        atomicAdd(&d_bnSqs[threadIdx.x], (double)sQ[threadIdx.x]);
    }
}

// ---------------- out = tanh(relu(a*ff+c) @ Wf2 + bf2) ----------------
__global__ void k_out(const float* __restrict__ Wf2,
                      const float* __restrict__ bf2,
                      float* __restrict__ out) {
    __shared__ float sA[32], sC[32], sW[64], sB[2];
    int t = threadIdx.x;
    if (t < 32) { sA[t] = d_bnA[t]; sC[t] = d_bnC[t]; }
    if (t < 64) sW[t] = Wf2[t];
    if (t < 2) sB[t] = bf2[t];
    __syncthreads();
    int i = blockIdx.x * blockDim.x + t;
    if (i >= N_NODES) return;
    float a0 = sB[0], a1 = sB[1];
    const float4* f4 = reinterpret_cast<const float4*>(d_g + (size_t)i * 32);
    #pragma unroll
    for (int j4 = 0; j4 < 8; j4++) {
        float4 v = f4[j4];
        int j = j4 * 4;
        float f;
        f = fmaxf(fmaf(sA[j + 0], v.x, sC[j + 0]), 0.f); a0 = fmaf(f, sW[2 * (j + 0)], a0); a1 = fmaf(f, sW[2 * (j + 0) + 1], a1);
        f = fmaxf(fmaf(sA[j + 1], v.y, sC[j + 1]), 0.f); a0 = fmaf(f, sW[2 * (j + 1)], a0); a1 = fmaf(f, sW[2 * (j + 1) + 1], a1);
        f = fmaxf(fmaf(sA[j + 2], v.z, sC[j + 2]), 0.f); a0 = fmaf(f, sW[2 * (j + 2)], a0); a1 = fmaf(f, sW[2 * (j + 2) + 1], a1);
        f = fmaxf(fmaf(sA[j + 3], v.w, sC[j + 3]), 0.f); a0 = fmaf(f, sW[2 * (j + 3)], a0); a1 = fmaf(f, sW[2 * (j + 3) + 1], a1);
    }
    out[2 * i]     = tanhf(a0);
    out[2 * i + 1] = tanhf(a1);
}

// ---------------- launch ----------------
extern "C" void kernel_launch(void* const* d_in, const int* in_sizes, int n_in,
                              void* d_out, int out_size) {
    const float* x    = (const float*)d_in[0];
    const int*   ei   = (const int*)d_in[1];
    const float* We   = (const float*)d_in[2];
    const float* be   = (const float*)d_in[3];
    const float* W1   = (const float*)d_in[4];
    const float* g1   = (const float*)d_in[6];
    const float* bt1  = (const float*)d_in[7];
    const float* W2   = (const float*)d_in[8];
    const float* g2   = (const float*)d_in[10];
    const float* bt2  = (const float*)d_in[11];
    const float* W3   = (const float*)d_in[12];
    const float* g3   = (const float*)d_in[14];
    const float* bt3  = (const float*)d_in[15];
    const float* Wf1  = (const float*)d_in[16];
    const float* gf   = (const float*)d_in[18];
    const float* btf  = (const float*)d_in[19];
    const float* Wf2  = (const float*)d_in[20];
    const float* bf2  = (const float*)d_in[21];
    float* out = (float*)d_out;
    // (b1/b2/b3/bf1 unused: uniform per-feature bias cancels inside BatchNorm)

    const int nb_scan = (N_NODES + 1023) / 1024;   // 98

    // graph preprocessing: degree -> dinv, CSC build ; W interleave prep
    k_zero_counts<<<(N_NODES + 255) / 256, 256>>>();
    k_count<<<(N_EDGES + 255) / 256, 256>>>(ei);
    k_dinv<<<(N_NODES + 255) / 256, 256>>>();
    k_scan_local<<<nb_scan, 1024>>>();
    k_scan_bsums<<<1, 128>>>(nb_scan);
    k_scan_add<<<nb_scan, 1024>>>();
    k_fill<<<(N_EDGES + 255) / 256, 256>>>(ei);
    k_prep_w<<<(3 * 64 * 128 + 255) / 256, 256>>>(W1, W2, W3);

    // encoder
    k_encoder<<<(N_NODES * 32 + 255) / 256, 256>>>(x, We, be);

    const int GB = 592;
    const int EW = (N_NODES * 32 + 255) / 256;

    // block 1: h0 -> h1
    k_zero_bn<<<1, 128>>>();
    k_gemm128<<<GB, 256>>>(0, 0);
    k_aggregate<<<GB, 256>>>();
    k_bn_finalize<<<1, 128>>>(g1, bt1, HID);
    k_bnrelu_res<<<EW, 256>>>(0, 1);

    // block 2: h1 -> h0
    k_zero_bn<<<1, 128>>>();
    k_gemm128<<<GB, 256>>>(1, 1);
    k_aggregate<<<GB, 256>>>();
    k_bn_finalize<<<1, 128>>>(g2, bt2, HID);
    k_bnrelu_res<<<EW, 256>>>(1, 0);

    // block 3: h0 -> h1
    k_zero_bn<<<1, 128>>>();
    k_gemm128<<<GB, 256>>>(2, 0);
    k_aggregate<<<GB, 256>>>();
    k_bn_finalize<<<1, 128>>>(g3, bt3, HID);
    k_bnrelu_res<<<EW, 256>>>(0, 1);

    // head: ff = h3 @ Wf1; BN; out = tanh(relu(BN(ff)) @ Wf2 + bf2)
    k_zero_bn<<<1, 128>>>();
    k_gemm32<<<GB, 256>>>(Wf1, 1);
    k_bnstats32<<<296, 256>>>();
    k_bn_finalize<<<1, 128>>>(gf, btf, 32);
    k_out<<<(N_NODES + 127) / 128, 128>>>(Wf2, bf2, out);

    (void)in_sizes; (void)n_in; (void)out_size;
}

// round 7
// speedup vs baseline: 1.2710x; 1.2710x over previous
#include <cuda_runtime.h>
#include <math.h>
#include <stdint.h>

#define N_NODES 100000
#define N_EDGES 1600000
#define HID 128
#define EPS 1e-5f

// ---------------- scratch (device globals; referenced ONLY in device code) ----------------
__device__ float  d_h0[N_NODES * HID];
__device__ float  d_h1[N_NODES * HID];
__device__ float  d_g [N_NODES * HID];   // dinv-scaled h@W ; head reuses as ff[N,32]
__device__ float  d_agg[N_NODES * HID];
__device__ float  d_dinv[N_NODES];
__device__ int    d_cnt[N_NODES];
__device__ int    d_cursor[N_NODES];
__device__ int    d_rowptr[N_NODES + 1];
__device__ int    d_col[N_EDGES];
__device__ int    d_bsums[128];
__device__ double d_bnSum[HID];
__device__ double d_bnSqs[HID];
__device__ float  d_bnA[HID];
__device__ float  d_bnC[HID];

// ---------------- helpers ----------------
__device__ __forceinline__ void fma4(float4& a, float s, const float4& w) {
    a.x = fmaf(s, w.x, a.x);
    a.y = fmaf(s, w.y, a.y);
    a.z = fmaf(s, w.z, a.z);
    a.w = fmaf(s, w.w, a.w);
}
__device__ __forceinline__ void add4(float4& a, const float4& v) {
    a.x += v.x; a.y += v.y; a.z += v.z; a.w += v.w;
}
__device__ __forceinline__ float* hbuf(int sel) { return sel == 0 ? d_h0 : d_h1; }

// ---------------- setup kernels ----------------
__global__ void k_zero_counts() {
    int i = blockIdx.x * blockDim.x + threadIdx.x;
    if (i < N_NODES) { d_cnt[i] = 0; d_cursor[i] = 0; }
}
__global__ void k_count(const int* __restrict__ ei) {
    int e = blockIdx.x * blockDim.x + threadIdx.x;
    if (e < N_EDGES) atomicAdd(&d_cnt[ei[N_EDGES + e]], 1);
}
__global__ void k_dinv() {
    int i = blockIdx.x * blockDim.x + threadIdx.x;
    if (i < N_NODES) d_dinv[i] = rsqrtf((float)d_cnt[i] + 1.0f);
}
__global__ void k_scan_local() {
    __shared__ int s[1024];
    int tid = threadIdx.x;
    int idx = blockIdx.x * 1024 + tid;
    int v = (idx < N_NODES) ? d_cnt[idx] : 0;
    s[tid] = v;
    __syncthreads();
    for (int off = 1; off < 1024; off <<= 1) {
        int t = (tid >= off) ? s[tid - off] : 0;
        __syncthreads();
        s[tid] += t;
        __syncthreads();
    }
    if (idx < N_NODES) d_rowptr[idx] = s[tid] - v;   // exclusive
    if (tid == 1023) d_bsums[blockIdx.x] = s[1023];
}
__global__ void k_scan_bsums(int nb) {
    __shared__ int sb[128];
    int t = threadIdx.x;
    sb[t] = (t < nb) ? d_bsums[t] : 0;
    __syncthreads();
    if (t == 0) {
        int run = 0;
        for (int i = 0; i < nb; i++) { int x = sb[i]; sb[i] = run; run += x; }
        d_rowptr[N_NODES] = run;
    }
    __syncthreads();
    if (t < nb) d_bsums[t] = sb[t];
}
__global__ void k_scan_add() {
    int idx = blockIdx.x * 1024 + threadIdx.x;
    if (idx < N_NODES) d_rowptr[idx] += d_bsums[blockIdx.x];
}
__global__ void k_fill(const int* __restrict__ ei) {
    int e = blockIdx.x * blockDim.x + threadIdx.x;
    if (e < N_EDGES) {
        int s = ei[e];
        int d = ei[N_EDGES + e];
        int pos = d_rowptr[d] + atomicAdd(&d_cursor[d], 1);
        d_col[pos] = s;
    }
}

// ---------------- core GEMM body: g[n] = dinv * (h @ W), h rows in registers ----------------
// warp computes 4 nodes x 128 outputs; each W row load feeds 16 FMAs
__device__ __forceinline__ void gemm_body(const float4* __restrict__ W4, int base, int lane,
                                          float4 h0, float4 h1, float4 h2, float4 h3,
                                          float4* __restrict__ O4) {
    const float4 z = make_float4(0.f, 0.f, 0.f, 0.f);
    float4 a0 = z, a1 = z, a2 = z, a3 = z;
    #pragma unroll 8
    for (int q = 0; q < 32; q++) {
        float4 w0 = __ldg(&W4[(q * 4 + 0) * 32 + lane]);
        float4 w1 = __ldg(&W4[(q * 4 + 1) * 32 + lane]);
        float4 w2 = __ldg(&W4[(q * 4 + 2) * 32 + lane]);
        float4 w3 = __ldg(&W4[(q * 4 + 3) * 32 + lane]);
        {
            float sx = __shfl_sync(0xffffffffu, h0.x, q);
            float sy = __shfl_sync(0xffffffffu, h0.y, q);
            float sz = __shfl_sync(0xffffffffu, h0.z, q);
            float sw = __shfl_sync(0xffffffffu, h0.w, q);
            fma4(a0, sx, w0); fma4(a0, sy, w1); fma4(a0, sz, w2); fma4(a0, sw, w3);
        }
        {
            float sx = __shfl_sync(0xffffffffu, h1.x, q);
            float sy = __shfl_sync(0xffffffffu, h1.y, q);
            float sz = __shfl_sync(0xffffffffu, h1.z, q);
            float sw = __shfl_sync(0xffffffffu, h1.w, q);
            fma4(a1, sx, w0); fma4(a1, sy, w1); fma4(a1, sz, w2); fma4(a1, sw, w3);
        }
        {
            float sx = __shfl_sync(0xffffffffu, h2.x, q);
            float sy = __shfl_sync(0xffffffffu, h2.y, q);
            float sz = __shfl_sync(0xffffffffu, h2.z, q);
            float sw = __shfl_sync(0xffffffffu, h2.w, q);
            fma4(a2, sx, w0); fma4(a2, sy, w1); fma4(a2, sz, w2); fma4(a2, sw, w3);
        }
        {
            float sx = __shfl_sync(0xffffffffu, h3.x, q);
            float sy = __shfl_sync(0xffffffffu, h3.y, q);
            float sz = __shfl_sync(0xffffffffu, h3.z, q);
            float sw = __shfl_sync(0xffffffffu, h3.w, q);
            fma4(a3, sx, w0); fma4(a3, sy, w1); fma4(a3, sz, w2); fma4(a3, sw, w3);
        }
    }
    {
        float s = d_dinv[base + 0];
        a0.x *= s; a0.y *= s; a0.z *= s; a0.w *= s;
        O4[(size_t)(base + 0) * 32 + lane] = a0;
    }
    {
        float s = d_dinv[base + 1];
        a1.x *= s; a1.y *= s; a1.z *= s; a1.w *= s;
        O4[(size_t)(base + 1) * 32 + lane] = a1;
    }
    {
        float s = d_dinv[base + 2];
        a2.x *= s; a2.y *= s; a2.z *= s; a2.w *= s;
        O4[(size_t)(base + 2) * 32 + lane] = a2;
    }
    {
        float s = d_dinv[base + 3];
        a3.x *= s; a3.y *= s; a3.z *= s; a3.w *= s;
        O4[(size_t)(base + 3) * 32 + lane] = a3;
    }
}

// ---------------- gemm1: h0 = relu(x@We+be) inline; d_g = dinv*(h0@W1); zero BN accs ----
__global__ void __launch_bounds__(256) k_gemm_first(const float* __restrict__ x,
                                                    const float* __restrict__ We,
                                                    const float* __restrict__ be,
                                                    const float* __restrict__ W1) {
    if (blockIdx.x == 0 && threadIdx.x < HID) {
        d_bnSum[threadIdx.x] = 0.0;
        d_bnSqs[threadIdx.x] = 0.0;
    }
    const int lane = threadIdx.x & 31;
    const int gwid = (blockIdx.x * blockDim.x + threadIdx.x) >> 5;
    const int nwarps = (gridDim.x * blockDim.x) >> 5;
    const float4* W4 = reinterpret_cast<const float4*>(W1);
    float4* H04 = reinterpret_cast<float4*>(d_h0);
    float4* O4 = reinterpret_cast<float4*>(d_g);
    float4 w0 = __ldg(&((const float4*)We)[lane]);
    float4 w1 = __ldg(&((const float4*)We)[32 + lane]);
    float4 b  = __ldg(&((const float4*)be)[lane]);

    for (int base = gwid * 4; base < N_NODES; base += nwarps * 4) {
        float4 h[4];
        #pragma unroll
        for (int n = 0; n < 4; n++) {
            float x0 = __ldg(&x[2 * (base + n)]), x1 = __ldg(&x[2 * (base + n) + 1]);
            h[n].x = fmaxf(fmaf(x0, w0.x, fmaf(x1, w1.x, b.x)), 0.f);
            h[n].y = fmaxf(fmaf(x0, w0.y, fmaf(x1, w1.y, b.y)), 0.f);
            h[n].z = fmaxf(fmaf(x0, w0.z, fmaf(x1, w1.z, b.z)), 0.f);
            h[n].w = fmaxf(fmaf(x0, w0.w, fmaf(x1, w1.w, b.w)), 0.f);
            H04[(size_t)(base + n) * 32 + lane] = h[n];
        }
        gemm_body(W4, base, lane, h[0], h[1], h[2], h[3], O4);
    }
}

// ---------------- gemm mid: h_new = relu(a*agg+c)+h_old (stored); d_g = dinv*(h_new@W) ---
__global__ void __launch_bounds__(256) k_gemm_mid(const float* __restrict__ W,
                                                  int hin_sel, int hout_sel) {
    const int lane = threadIdx.x & 31;
    const int gwid = (blockIdx.x * blockDim.x + threadIdx.x) >> 5;
    const int nwarps = (gridDim.x * blockDim.x) >> 5;
    const float4* W4 = reinterpret_cast<const float4*>(W);
    const float4* A4 = reinterpret_cast<const float4*>(d_agg);
    const float4* HI4 = reinterpret_cast<const float4*>(hbuf(hin_sel));
    float4* HO4 = reinterpret_cast<float4*>(hbuf(hout_sel));
    float4* O4 = reinterpret_cast<float4*>(d_g);
    float4 ba = ((const float4*)d_bnA)[lane];
    float4 bc = ((const float4*)d_bnC)[lane];

    for (int base = gwid * 4; base < N_NODES; base += nwarps * 4) {
        float4 h[4];
        #pragma unroll
        for (int n = 0; n < 4; n++) {
            float4 v = A4[(size_t)(base + n) * 32 + lane];
            float4 ho = HI4[(size_t)(base + n) * 32 + lane];
            h[n].x = fmaxf(fmaf(ba.x, v.x, bc.x), 0.f) + ho.x;
            h[n].y = fmaxf(fmaf(ba.y, v.y, bc.y), 0.f) + ho.y;
            h[n].z = fmaxf(fmaf(ba.z, v.z, bc.z), 0.f) + ho.z;
            h[n].w = fmaxf(fmaf(ba.w, v.w, bc.w), 0.f) + ho.w;
            HO4[(size_t)(base + n) * 32 + lane] = h[n];
        }
        gemm_body(W4, base, lane, h[0], h[1], h[2], h[3], O4);
    }
}

// ---------------- aggregation: agg[i] = dinv[i]*(sum_in g[src] + g[i]); BN partials ---
__global__ void k_aggregate() {
    __shared__ float sS[HID];
    __shared__ float sQ[HID];
    if (threadIdx.x < HID) { sS[threadIdx.x] = 0.f; sQ[threadIdx.x] = 0.f; }
    __syncthreads();

    const int lane = threadIdx.x & 31;
    const int gwid = (blockIdx.x * blockDim.x + threadIdx.x) >> 5;
    const int nwarps = (gridDim.x * blockDim.x) >> 5;
    const float4* g4 = reinterpret_cast<const float4*>(d_g);
    float4* agg4 = reinterpret_cast<float4*>(d_agg);

    float4 lsum = make_float4(0.f, 0.f, 0.f, 0.f);
    float4 lsq  = make_float4(0.f, 0.f, 0.f, 0.f);

    for (int i = gwid; i < N_NODES; i += nwarps) {
        float4 acc = g4[(size_t)i * 32 + lane];   // self loop
        int e0 = d_rowptr[i], e1 = d_rowptr[i + 1];
        int e = e0;
        for (; e + 2 <= e1; e += 2) {             // unroll x2 for MLP
            int s0 = __ldg(&d_col[e]);
            int s1 = __ldg(&d_col[e + 1]);
            float4 v0 = __ldg(&g4[(size_t)s0 * 32 + lane]);
            float4 v1 = __ldg(&g4[(size_t)s1 * 32 + lane]);
            add4(acc, v0);
            add4(acc, v1);
        }
        if (e < e1) {
            int s0 = __ldg(&d_col[e]);
            float4 v0 = __ldg(&g4[(size_t)s0 * 32 + lane]);
            add4(acc, v0);
        }
        float dv = d_dinv[i];
        acc.x *= dv; acc.y *= dv; acc.z *= dv; acc.w *= dv;
        agg4[(size_t)i * 32 + lane] = acc;
        add4(lsum, acc);
        lsq.x = fmaf(acc.x, acc.x, lsq.x);
        lsq.y = fmaf(acc.y, acc.y, lsq.y);
        lsq.z = fmaf(acc.z, acc.z, lsq.z);
        lsq.w = fmaf(acc.w, acc.w, lsq.w);
    }
    int f = 4 * lane;
    atomicAdd(&sS[f + 0], lsum.x); atomicAdd(&sS[f + 1], lsum.y);
    atomicAdd(&sS[f + 2], lsum.z); atomicAdd(&sS[f + 3], lsum.w);
    atomicAdd(&sQ[f + 0], lsq.x);  atomicAdd(&sQ[f + 1], lsq.y);
    atomicAdd(&sQ[f + 2], lsq.z);  atomicAdd(&sQ[f + 3], lsq.w);
    __syncthreads();
    if (threadIdx.x < HID) {
        atomicAdd(&d_bnSum[threadIdx.x], (double)sS[threadIdx.x]);
        atomicAdd(&d_bnSqs[threadIdx.x], (double)sQ[threadIdx.x]);
    }
}

// ---------------- BN coeffs: a = gamma*rsqrt(var+eps), c = beta - mean*a; zero accs ----
__global__ void k_bn_finalize(const float* __restrict__ gamma,
                              const float* __restrict__ beta, int nfeat) {
    int t = threadIdx.x;
    if (t < nfeat) {
        double mean = d_bnSum[t] / (double)N_NODES;
        double var  = d_bnSqs[t] / (double)N_NODES - mean * mean;
        float a = gamma[t] * rsqrtf((float)var + EPS);
        d_bnA[t] = a;
        d_bnC[t] = beta[t] - (float)mean * a;
        d_bnSum[t] = 0.0;       // ready for next layer's stats
        d_bnSqs[t] = 0.0;
    }
}

// ---------------- head gemm: h3 = relu(a*agg+c)+h2 inline; ff = h3@Wf1; BN stats ------
__global__ void k_gemm32_fused(const float* __restrict__ W, int hin_sel) {
    __shared__ float sW[HID * 32];
    __shared__ float sS[32];
    __shared__ float sQ[32];
    for (int i = threadIdx.x; i < HID * 32; i += blockDim.x) sW[i] = W[i];
    if (threadIdx.x < 32) { sS[threadIdx.x] = 0.f; sQ[threadIdx.x] = 0.f; }
    __syncthreads();
    const int lane = threadIdx.x & 31;
    const int gwid = (blockIdx.x * blockDim.x + threadIdx.x) >> 5;
    const int nwarps = (gridDim.x * blockDim.x) >> 5;
    const float4* A4 = reinterpret_cast<const float4*>(d_agg);
    const float4* HI4 = reinterpret_cast<const float4*>(hbuf(hin_sel));
    float4 ba = ((const float4*)d_bnA)[lane];
    float4 bc = ((const float4*)d_bnC)[lane];
    float s = 0.f, q = 0.f;

    for (int i = gwid; i < N_NODES; i += nwarps) {
        float4 v = A4[(size_t)i * 32 + lane];
        float4 ho = HI4[(size_t)i * 32 + lane];
        float4 h;
        h.x = fmaxf(fmaf(ba.x, v.x, bc.x), 0.f) + ho.x;
        h.y = fmaxf(fmaf(ba.y, v.y, bc.y), 0.f) + ho.y;
        h.z = fmaxf(fmaf(ba.z, v.z, bc.z), 0.f) + ho.z;
        h.w = fmaxf(fmaf(ba.w, v.w, bc.w), 0.f) + ho.w;
        float acc = 0.f;
        #pragma unroll 8
        for (int p = 0; p < 32; p++) {
            float sx = __shfl_sync(0xffffffffu, h.x, p);
            float sy = __shfl_sync(0xffffffffu, h.y, p);
            float sz = __shfl_sync(0xffffffffu, h.z, p);
            float sw = __shfl_sync(0xffffffffu, h.w, p);
            acc = fmaf(sx, sW[(4 * p + 0) * 32 + lane], acc);
            acc = fmaf(sy, sW[(4 * p + 1) * 32 + lane], acc);
            acc = fmaf(sz, sW[(4 * p + 2) * 32 + lane], acc);
            acc = fmaf(sw, sW[(4 * p + 3) * 32 + lane], acc);
        }
        d_g[(size_t)i * 32 + lane] = acc;
        s += acc;
        q = fmaf(acc, acc, q);
    }
    atomicAdd(&sS[lane], s);
    atomicAdd(&sQ[lane], q);
    __syncthreads();
    if (threadIdx.x < 32) {
        atomicAdd(&d_bnSum[threadIdx.x], (double)sS[threadIdx.x]);
        atomicAdd(&d_bnSqs[threadIdx.x], (double)sQ[threadIdx.x]);
    }
}

// ---------------- out = tanh(relu(a*ff+c) @ Wf2 + bf2) ----------------
__global__ void k_out(const float* __restrict__ Wf2,
                      const float* __restrict__ bf2,
                      float* __restrict__ out) {
    __shared__ float sA[32], sC[32], sW[64], sB[2];
    int t = threadIdx.x;
    if (t < 32) { sA[t] = d_bnA[t]; sC[t] = d_bnC[t]; }
    if (t < 64) sW[t] = Wf2[t];
    if (t < 2) sB[t] = bf2[t];
    __syncthreads();
    int i = blockIdx.x * blockDim.x + t;
    if (i >= N_NODES) return;
    float a0 = sB[0], a1 = sB[1];
    const float4* f4 = reinterpret_cast<const float4*>(d_g + (size_t)i * 32);
    #pragma unroll
    for (int j4 = 0; j4 < 8; j4++) {
        float4 v = f4[j4];
        int j = j4 * 4;
        float f;
        f = fmaxf(fmaf(sA[j + 0], v.x, sC[j + 0]), 0.f); a0 = fmaf(f, sW[2 * (j + 0)], a0); a1 = fmaf(f, sW[2 * (j + 0) + 1], a1);
        f = fmaxf(fmaf(sA[j + 1], v.y, sC[j + 1]), 0.f); a0 = fmaf(f, sW[2 * (j + 1)], a0); a1 = fmaf(f, sW[2 * (j + 1) + 1], a1);
        f = fmaxf(fmaf(sA[j + 2], v.z, sC[j + 2]), 0.f); a0 = fmaf(f, sW[2 * (j + 2)], a0); a1 = fmaf(f, sW[2 * (j + 2) + 1], a1);
        f = fmaxf(fmaf(sA[j + 3], v.w, sC[j + 3]), 0.f); a0 = fmaf(f, sW[2 * (j + 3)], a0); a1 = fmaf(f, sW[2 * (j + 3) + 1], a1);
    }
    out[2 * i]     = tanhf(a0);
    out[2 * i + 1] = tanhf(a1);
}

// ---------------- launch ----------------
extern "C" void kernel_launch(void* const* d_in, const int* in_sizes, int n_in,
                              void* d_out, int out_size) {
    const float* x    = (const float*)d_in[0];
    const int*   ei   = (const int*)d_in[1];
    const float* We   = (const float*)d_in[2];
    const float* be   = (const float*)d_in[3];
    const float* W1   = (const float*)d_in[4];
    const float* g1   = (const float*)d_in[6];
    const float* bt1  = (const float*)d_in[7];
    const float* W2   = (const float*)d_in[8];
    const float* g2   = (const float*)d_in[10];
    const float* bt2  = (const float*)d_in[11];
    const float* W3   = (const float*)d_in[12];
    const float* g3   = (const float*)d_in[14];
    const float* bt3  = (const float*)d_in[15];
    const float* Wf1  = (const float*)d_in[16];
    const float* gf   = (const float*)d_in[18];
    const float* btf  = (const float*)d_in[19];
    const float* Wf2  = (const float*)d_in[20];
    const float* bf2  = (const float*)d_in[21];
    float* out = (float*)d_out;
    // (b1/b2/b3/bf1 unused: uniform per-feature bias cancels inside BatchNorm)

    const int nb_scan = (N_NODES + 1023) / 1024;   // 98
    const int GB = 592;

    // graph preprocessing: degree -> dinv, CSC build
    k_zero_counts<<<(N_NODES + 255) / 256, 256>>>();
    k_count<<<(N_EDGES + 255) / 256, 256>>>(ei);
    k_dinv<<<(N_NODES + 255) / 256, 256>>>();
    k_scan_local<<<nb_scan, 1024>>>();
    k_scan_bsums<<<1, 128>>>(nb_scan);
    k_scan_add<<<nb_scan, 1024>>>();
    k_fill<<<(N_EDGES + 255) / 256, 256>>>(ei);

    // block 1: encoder fused; h0 -> g
    k_gemm_first<<<GB, 256>>>(x, We, be, W1);
    k_aggregate<<<GB, 256>>>();
    k_bn_finalize<<<1, 128>>>(g1, bt1, HID);

    // block 2: bnrelu(block1) fused; h0 -> h1 -> g
    k_gemm_mid<<<GB, 256>>>(W2, 0, 1);
    k_aggregate<<<GB, 256>>>();
    k_bn_finalize<<<1, 128>>>(g2, bt2, HID);

    // block 3: bnrelu(block2) fused; h1 -> h0 -> g
    k_gemm_mid<<<GB, 256>>>(W3, 1, 0);
    k_aggregate<<<GB, 256>>>();
    k_bn_finalize<<<1, 128>>>(g3, bt3, HID);

    // head: bnrelu(block3) fused; h0 -> h3 (regs) -> ff in d_g, stats fused
    k_gemm32_fused<<<GB, 256>>>(Wf1, 0);
    k_bn_finalize<<<1, 128>>>(gf, btf, 32);
    k_out<<<(N_NODES + 127) / 128, 128>>>(Wf2, bf2, out);

    (void)in_sizes; (void)n_in; (void)out_size;
}

// round 9
// speedup vs baseline: 1.6759x; 1.3186x over previous
#include <cuda_runtime.h>
#include <math.h>
#include <stdint.h>

#define N_NODES 100000
#define N_EDGES 1600000
#define HID 128
#define EPS 1e-5f
#define N_TILES 782          // ceil(100000/128)
#define SM_STRIDE 136        // floats per staged row; 136 % 32 == 8 -> conflict-free frag LDS
#define SMEM_MMA (8 * 16 * SM_STRIDE * 4)   // 69632 B

// ---------------- scratch (device globals; referenced ONLY in device code) ----------------
__device__ float  d_h0[N_NODES * HID];
__device__ float  d_h1[N_NODES * HID];
__device__ float  d_g [N_NODES * HID];   // dinv-scaled h@W ; head reuses as ff[N,32]
__device__ float  d_agg[N_NODES * HID];
__device__ float  d_dinv[N_NODES];
__device__ int    d_cnt[N_NODES];
__device__ int    d_cursor[N_NODES];
__device__ int    d_rowptr[N_NODES + 1];
__device__ int    d_col[N_EDGES];
__device__ int    d_bsums[128];
__device__ double d_bnSum[HID];
__device__ double d_bnSqs[HID];
__device__ float  d_bnA[HID];
__device__ float  d_bnC[HID];
// B-fragment images: per (layer, kt, nt, lane): uint4 {bhi0, bhi1, blo0, blo1}
__device__ uint4  d_Wfrag[3 * 128 * 32];

// ---------------- helpers ----------------
__device__ __forceinline__ void add4(float4& a, const float4& v) {
    a.x += v.x; a.y += v.y; a.z += v.z; a.w += v.w;
}
__device__ __forceinline__ float* hbuf(int sel) { return sel == 0 ? d_h0 : d_h1; }

__device__ __forceinline__ uint32_t pack_bf16x2(float lo, float hi) {
    uint32_t d;
    asm("cvt.rn.bf16x2.f32 %0, %2, %1;" : "=r"(d) : "f"(lo), "f"(hi));
    return d;
}
__device__ __forceinline__ float bf_lo(uint32_t v) { return __uint_as_float(v << 16); }
__device__ __forceinline__ float bf_hi(uint32_t v) { return __uint_as_float(v & 0xffff0000u); }

// split float2 -> bf16x2 hi image + bf16x2 residual image
__device__ __forceinline__ void split2(float a, float b, uint32_t& hi, uint32_t& lo) {
    hi = pack_bf16x2(a, b);
    lo = pack_bf16x2(a - bf_lo(hi), b - bf_hi(hi));
}

__device__ __forceinline__ void mma_bf16(float c[4], uint32_t a0, uint32_t a1,
                                         uint32_t a2, uint32_t a3,
                                         uint32_t b0, uint32_t b1) {
    asm volatile(
        "mma.sync.aligned.m16n8k16.row.col.f32.bf16.bf16.f32 "
        "{%0,%1,%2,%3}, {%4,%5,%6,%7}, {%8,%9}, {%0,%1,%2,%3};"
        : "+f"(c[0]), "+f"(c[1]), "+f"(c[2]), "+f"(c[3])
        : "r"(a0), "r"(a1), "r"(a2), "r"(a3), "r"(b0), "r"(b1));
}

// ---------------- setup kernels ----------------
__global__ void k_zero_counts() {
    int i = blockIdx.x * blockDim.x + threadIdx.x;
    if (i < N_NODES) { d_cnt[i] = 0; d_cursor[i] = 0; }
}
__global__ void k_count(const int* __restrict__ ei) {
    int e = blockIdx.x * blockDim.x + threadIdx.x;
    if (e < N_EDGES) atomicAdd(&d_cnt[ei[N_EDGES + e]], 1);
}
__global__ void k_dinv() {
    int i = blockIdx.x * blockDim.x + threadIdx.x;
    if (i < N_NODES) d_dinv[i] = rsqrtf((float)d_cnt[i] + 1.0f);
}
__global__ void k_scan_local() {
    __shared__ int s[1024];
    int tid = threadIdx.x;
    int idx = blockIdx.x * 1024 + tid;
    int v = (idx < N_NODES) ? d_cnt[idx] : 0;
    s[tid] = v;
    __syncthreads();
    for (int off = 1; off < 1024; off <<= 1) {
        int t = (tid >= off) ? s[tid - off] : 0;
        __syncthreads();
        s[tid] += t;
        __syncthreads();
    }
    if (idx < N_NODES) d_rowptr[idx] = s[tid] - v;   // exclusive
    if (tid == 1023) d_bsums[blockIdx.x] = s[1023];
}
__global__ void k_scan_bsums(int nb) {
    __shared__ int sb[128];
    int t = threadIdx.x;
    sb[t] = (t < nb) ? d_bsums[t] : 0;
    __syncthreads();
    if (t == 0) {
        int run = 0;
        for (int i = 0; i < nb; i++) { int x = sb[i]; sb[i] = run; run += x; }
        d_rowptr[N_NODES] = run;
    }
    __syncthreads();
    if (t < nb) d_bsums[t] = sb[t];
}
__global__ void k_scan_add() {
    int idx = blockIdx.x * 1024 + threadIdx.x;
    if (idx < N_NODES) d_rowptr[idx] += d_bsums[blockIdx.x];
}
__global__ void k_fill(const int* __restrict__ ei) {
    int e = blockIdx.x * blockDim.x + threadIdx.x;
    if (e < N_EDGES) {
        int s = ei[e];
        int d = ei[N_EDGES + e];
        int pos = d_rowptr[d] + atomicAdd(&d_cursor[d], 1);
        d_col[pos] = s;
    }
}

// ---------------- W prep: build per-(kt,nt,lane) B fragments, bf16 hi/lo ----------------
// D = H @ W -> mma B fragment (k16 x n8, "col"): b0 = {W[k=kt*16+2t][n], W[k+1][n]},
// b1 = {W[k=kt*16+2t+8][n], W[k+1][n]},  n = nt*8 + g,  g = lane>>2, t = lane&3.
__global__ void k_prep_wfrag(const float* __restrict__ W1,
                             const float* __restrict__ W2,
                             const float* __restrict__ W3) {
    int idx = blockIdx.x * blockDim.x + threadIdx.x;
    if (idx >= 3 * 8 * 16 * 32) return;
    int lane = idx & 31;
    int nt = (idx >> 5) & 15;
    int kt = (idx >> 9) & 7;
    int L  = idx >> 12;
    const float* W = (L == 0) ? W1 : (L == 1) ? W2 : W3;
    int g = lane >> 2, t = lane & 3;
    int n = nt * 8 + g;
    int k0 = kt * 16 + 2 * t;
    int k1 = kt * 16 + 2 * t + 8;
    uint32_t h0, l0, h1, l1;
    split2(W[k0 * 128 + n], W[(k0 + 1) * 128 + n], h0, l0);
    split2(W[k1 * 128 + n], W[(k1 + 1) * 128 + n], h1, l1);
    uint4 v; v.x = h0; v.y = h1; v.z = l0; v.w = l1;
    d_Wfrag[(L * 128 + kt * 16 + nt) * 32 + lane] = v;
}

// ---------------- tensor GEMM: d_g = dinv * (h_new @ W_layer) ----------------
// CTA = 128 rows, 8 warps x 16 rows. Phase1: compute h_new (encoder for first layer,
// BN+ReLU+residual otherwise), store to gmem + warp-private smem slice.
// Phase2: build split-bf16 A fragments. Phase3: 3-pass mma, per-nt epilogue.
__global__ void __launch_bounds__(256, 2) k_mma_gemm(
    const float* __restrict__ x, const float* __restrict__ We,
    const float* __restrict__ be,
    int layer, int hin_sel, int hout_sel, int first) {
    extern __shared__ float smf[];
    const int lane = threadIdx.x & 31;
    const int wid = threadIdx.x >> 5;
    const int tile = blockIdx.x;
    float* sw = smf + wid * 16 * SM_STRIDE;
    const int rbase = tile * 128 + wid * 16;

    if (first && blockIdx.x == 0 && threadIdx.x < HID) {
        d_bnSum[threadIdx.x] = 0.0;
        d_bnSqs[threadIdx.x] = 0.0;
    }

    // ---- phase 1: h_new for this warp's 16 rows ----
    if (first) {
        float4 w0 = __ldg(&((const float4*)We)[lane]);
        float4 w1 = __ldg(&((const float4*)We)[32 + lane]);
        float4 b  = __ldg(&((const float4*)be)[lane]);
        float4* H04 = reinterpret_cast<float4*>(d_h0);
        #pragma unroll 4
        for (int r = 0; r < 16; r++) {
            int row = rbase + r;
            int rs = (row < N_NODES) ? row : N_NODES - 1;
            float x0 = __ldg(&x[2 * rs]), x1 = __ldg(&x[2 * rs + 1]);
            float4 h;
            h.x = fmaxf(fmaf(x0, w0.x, fmaf(x1, w1.x, b.x)), 0.f);
            h.y = fmaxf(fmaf(x0, w0.y, fmaf(x1, w1.y, b.y)), 0.f);
            h.z = fmaxf(fmaf(x0, w0.z, fmaf(x1, w1.z, b.z)), 0.f);
            h.w = fmaxf(fmaf(x0, w0.w, fmaf(x1, w1.w, b.w)), 0.f);
            if (row < N_NODES) H04[(size_t)row * 32 + lane] = h;
            *reinterpret_cast<float4*>(sw + r * SM_STRIDE + 4 * lane) = h;
        }
    } else {
        float4 ba = ((const float4*)d_bnA)[lane];
        float4 bc = ((const float4*)d_bnC)[lane];
        const float4* A4 = reinterpret_cast<const float4*>(d_agg);
        const float4* HI4 = reinterpret_cast<const float4*>(hbuf(hin_sel));
        float4* HO4 = reinterpret_cast<float4*>(hbuf(hout_sel));
        #pragma unroll 4
        for (int r = 0; r < 16; r++) {
            int row = rbase + r;
            int rs = (row < N_NODES) ? row : N_NODES - 1;
            float4 v = A4[(size_t)rs * 32 + lane];
            float4 ho = HI4[(size_t)rs * 32 + lane];
            float4 h;
            h.x = fmaxf(fmaf(ba.x, v.x, bc.x), 0.f) + ho.x;
            h.y = fmaxf(fmaf(ba.y, v.y, bc.y), 0.f) + ho.y;
            h.z = fmaxf(fmaf(ba.z, v.z, bc.z), 0.f) + ho.z;
            h.w = fmaxf(fmaf(ba.w, v.w, bc.w), 0.f) + ho.w;
            if (row < N_NODES) HO4[(size_t)row * 32 + lane] = h;
            *reinterpret_cast<float4*>(sw + r * SM_STRIDE + 4 * lane) = h;
        }
    }
    __syncwarp();

    // ---- phase 2: A fragments (split bf16), 8 k-tiles ----
    const int g = lane >> 2, t = lane & 3;
    const float* r0p = sw + g * SM_STRIDE;
    const float* r1p = sw + (g + 8) * SM_STRIDE;
    uint32_t ah[32], al[32];
    #pragma unroll
    for (int kt = 0; kt < 8; kt++) {
        float2 p0 = *reinterpret_cast<const float2*>(r0p + 16 * kt + 2 * t);
        float2 p1 = *reinterpret_cast<const float2*>(r1p + 16 * kt + 2 * t);
        float2 p2 = *reinterpret_cast<const float2*>(r0p + 16 * kt + 2 * t + 8);
        float2 p3 = *reinterpret_cast<const float2*>(r1p + 16 * kt + 2 * t + 8);
        split2(p0.x, p0.y, ah[4 * kt + 0], al[4 * kt + 0]);
        split2(p1.x, p1.y, ah[4 * kt + 1], al[4 * kt + 1]);
        split2(p2.x, p2.y, ah[4 * kt + 2], al[4 * kt + 2]);
        split2(p3.x, p3.y, ah[4 * kt + 3], al[4 * kt + 3]);
    }

    // ---- phase 3: mma over 16 n-tiles (2 at a time), 3-pass split bf16 ----
    const uint4* Wf = &d_Wfrag[layer * 128 * 32];
    int row0 = rbase + g, row1 = rbase + g + 8;
    float dv0 = d_dinv[(row0 < N_NODES) ? row0 : 0];
    float dv1 = d_dinv[(row1 < N_NODES) ? row1 : 0];

    #pragma unroll
    for (int ntp = 0; ntp < 8; ntp++) {
        float c0[4] = {0.f, 0.f, 0.f, 0.f};
        float c1[4] = {0.f, 0.f, 0.f, 0.f};
        #pragma unroll
        for (int kt = 0; kt < 8; kt++) {
            uint4 B0 = __ldg(&Wf[(kt * 16 + 2 * ntp) * 32 + lane]);
            uint4 B1 = __ldg(&Wf[(kt * 16 + 2 * ntp + 1) * 32 + lane]);
            uint32_t a0 = ah[4 * kt], a1 = ah[4 * kt + 1], a2 = ah[4 * kt + 2], a3 = ah[4 * kt + 3];
            uint32_t l0 = al[4 * kt], l1 = al[4 * kt + 1], l2 = al[4 * kt + 2], l3 = al[4 * kt + 3];
            mma_bf16(c0, a0, a1, a2, a3, B0.x, B0.y);   // Ah * Bh
            mma_bf16(c0, l0, l1, l2, l3, B0.x, B0.y);   // Al * Bh
            mma_bf16(c0, a0, a1, a2, a3, B0.z, B0.w);   // Ah * Bl
            mma_bf16(c1, a0, a1, a2, a3, B1.x, B1.y);
            mma_bf16(c1, l0, l1, l2, l3, B1.x, B1.y);
            mma_bf16(c1, a0, a1, a2, a3, B1.z, B1.w);
        }
        int col0 = (2 * ntp) * 8 + 2 * t;
        int col1 = (2 * ntp + 1) * 8 + 2 * t;
        if (row0 < N_NODES) {
            float2 o;
            o.x = c0[0] * dv0; o.y = c0[1] * dv0;
            *reinterpret_cast<float2*>(d_g + (size_t)row0 * 128 + col0) = o;
            o.x = c1[0] * dv0; o.y = c1[1] * dv0;
            *reinterpret_cast<float2*>(d_g + (size_t)row0 * 128 + col1) = o;
        }
        if (row1 < N_NODES) {
            float2 o;
            o.x = c0[2] * dv1; o.y = c0[3] * dv1;
            *reinterpret_cast<float2*>(d_g + (size_t)row1 * 128 + col0) = o;
            o.x = c1[2] * dv1; o.y = c1[3] * dv1;
            *reinterpret_cast<float2*>(d_g + (size_t)row1 * 128 + col1) = o;
        }
    }
}

// ---------------- aggregation: agg[i] = dinv[i]*(sum_in g[src] + g[i]); BN partials ---
__global__ void k_aggregate() {
    __shared__ float sS[HID];
    __shared__ float sQ[HID];
    if (threadIdx.x < HID) { sS[threadIdx.x] = 0.f; sQ[threadIdx.x] = 0.f; }
    __syncthreads();

    const int lane = threadIdx.x & 31;
    const int gwid = (blockIdx.x * blockDim.x + threadIdx.x) >> 5;
    const int nwarps = (gridDim.x * blockDim.x) >> 5;
    const float4* g4 = reinterpret_cast<const float4*>(d_g);
    float4* agg4 = reinterpret_cast<float4*>(d_agg);

    float4 lsum = make_float4(0.f, 0.f, 0.f, 0.f);
    float4 lsq  = make_float4(0.f, 0.f, 0.f, 0.f);

    for (int i = gwid; i < N_NODES; i += nwarps) {
        float4 acc = g4[(size_t)i * 32 + lane];   // self loop
        int e0 = d_rowptr[i], e1 = d_rowptr[i + 1];
        int e = e0;
        for (; e + 2 <= e1; e += 2) {             // unroll x2 for MLP
            int s0 = __ldg(&d_col[e]);
            int s1 = __ldg(&d_col[e + 1]);
            float4 v0 = __ldg(&g4[(size_t)s0 * 32 + lane]);
            float4 v1 = __ldg(&g4[(size_t)s1 * 32 + lane]);
            add4(acc, v0);
            add4(acc, v1);
        }
        if (e < e1) {
            int s0 = __ldg(&d_col[e]);
            float4 v0 = __ldg(&g4[(size_t)s0 * 32 + lane]);
            add4(acc, v0);
        }
        float dv = d_dinv[i];
        acc.x *= dv; acc.y *= dv; acc.z *= dv; acc.w *= dv;
        agg4[(size_t)i * 32 + lane] = acc;
        add4(lsum, acc);
        lsq.x = fmaf(acc.x, acc.x, lsq.x);
        lsq.y = fmaf(acc.y, acc.y, lsq.y);
        lsq.z = fmaf(acc.z, acc.z, lsq.z);
        lsq.w = fmaf(acc.w, acc.w, lsq.w);
    }
    int f = 4 * lane;
    atomicAdd(&sS[f + 0], lsum.x); atomicAdd(&sS[f + 1], lsum.y);
    atomicAdd(&sS[f + 2], lsum.z); atomicAdd(&sS[f + 3], lsum.w);
    atomicAdd(&sQ[f + 0], lsq.x);  atomicAdd(&sQ[f + 1], lsq.y);
    atomicAdd(&sQ[f + 2], lsq.z);  atomicAdd(&sQ[f + 3], lsq.w);
    __syncthreads();
    if (threadIdx.x < HID) {
        atomicAdd(&d_bnSum[threadIdx.x], (double)sS[threadIdx.x]);
        atomicAdd(&d_bnSqs[threadIdx.x], (double)sQ[threadIdx.x]);
    }
}

// ---------------- BN coeffs: a = gamma*rsqrt(var+eps), c = beta - mean*a; zero accs ----
__global__ void k_bn_finalize(const float* __restrict__ gamma,
                              const float* __restrict__ beta, int nfeat) {
    int t = threadIdx.x;
    if (t < nfeat) {
        double mean = d_bnSum[t] / (double)N_NODES;
        double var  = d_bnSqs[t] / (double)N_NODES - mean * mean;
        float a = gamma[t] * rsqrtf((float)var + EPS);
        d_bnA[t] = a;
        d_bnC[t] = beta[t] - (float)mean * a;
        d_bnSum[t] = 0.0;       // ready for next layer's stats
        d_bnSqs[t] = 0.0;
    }
}

// ---------------- head gemm: h3 = relu(a*agg+c)+h2 inline; ff = h3@Wf1; BN stats ------
__global__ void k_gemm32_fused(const float* __restrict__ W, int hin_sel) {
    __shared__ float sW[HID * 32];
    __shared__ float sS[32];
    __shared__ float sQ[32];
    for (int i = threadIdx.x; i < HID * 32; i += blockDim.x) sW[i] = W[i];
    if (threadIdx.x < 32) { sS[threadIdx.x] = 0.f; sQ[threadIdx.x] = 0.f; }
    __syncthreads();
    const int lane = threadIdx.x & 31;
    const int gwid = (blockIdx.x * blockDim.x + threadIdx.x) >> 5;
    const int nwarps = (gridDim.x * blockDim.x) >> 5;
    const float4* A4 = reinterpret_cast<const float4*>(d_agg);
    const float4* HI4 = reinterpret_cast<const float4*>(hbuf(hin_sel));
    float4 ba = ((const float4*)d_bnA)[lane];
    float4 bc = ((const float4*)d_bnC)[lane];
    float s = 0.f, q = 0.f;

    for (int i = gwid; i < N_NODES; i += nwarps) {
        float4 v = A4[(size_t)i * 32 + lane];
        float4 ho = HI4[(size_t)i * 32 + lane];
        float4 h;
        h.x = fmaxf(fmaf(ba.x, v.x, bc.x), 0.f) + ho.x;
        h.y = fmaxf(fmaf(ba.y, v.y, bc.y), 0.f) + ho.y;
        h.z = fmaxf(fmaf(ba.z, v.z, bc.z), 0.f) + ho.z;
        h.w = fmaxf(fmaf(ba.w, v.w, bc.w), 0.f) + ho.w;
        float acc = 0.f;
        #pragma unroll 8
        for (int p = 0; p < 32; p++) {
            float sx = __shfl_sync(0xffffffffu, h.x, p);
            float sy = __shfl_sync(0xffffffffu, h.y, p);
            float sz = __shfl_sync(0xffffffffu, h.z, p);
            float sw = __shfl_sync(0xffffffffu, h.w, p);
            acc = fmaf(sx, sW[(4 * p + 0) * 32 + lane], acc);
            acc = fmaf(sy, sW[(4 * p + 1) * 32 + lane], acc);
            acc = fmaf(sz, sW[(4 * p + 2) * 32 + lane], acc);
            acc = fmaf(sw, sW[(4 * p + 3) * 32 + lane], acc);
        }
        d_g[(size_t)i * 32 + lane] = acc;
        s += acc;
        q = fmaf(acc, acc, q);
    }
    atomicAdd(&sS[lane], s);
    atomicAdd(&sQ[lane], q);
    __syncthreads();
    if (threadIdx.x < 32) {
        atomicAdd(&d_bnSum[threadIdx.x], (double)sS[threadIdx.x]);
        atomicAdd(&d_bnSqs[threadIdx.x], (double)sQ[threadIdx.x]);
    }
}

// ---------------- out = tanh(relu(a*ff+c) @ Wf2 + bf2) ----------------
__global__ void k_out(const float* __restrict__ Wf2,
                      const float* __restrict__ bf2,
                      float* __restrict__ out) {
    __shared__ float sA[32], sC[32], sW[64], sB[2];
    int t = threadIdx.x;
    if (t < 32) { sA[t] = d_bnA[t]; sC[t] = d_bnC[t]; }
    if (t < 64) sW[t] = Wf2[t];
    if (t < 2) sB[t] = bf2[t];
    __syncthreads();
    int i = blockIdx.x * blockDim.x + t;
    if (i >= N_NODES) return;
    float a0 = sB[0], a1 = sB[1];
    const float4* f4 = reinterpret_cast<const float4*>(d_g + (size_t)i * 32);
    #pragma unroll
    for (int j4 = 0; j4 < 8; j4++) {
        float4 v = f4[j4];
        int j = j4 * 4;
        float f;
        f = fmaxf(fmaf(sA[j + 0], v.x, sC[j + 0]), 0.f); a0 = fmaf(f, sW[2 * (j + 0)], a0); a1 = fmaf(f, sW[2 * (j + 0) + 1], a1);
        f = fmaxf(fmaf(sA[j + 1], v.y, sC[j + 1]), 0.f); a0 = fmaf(f, sW[2 * (j + 1)], a0); a1 = fmaf(f, sW[2 * (j + 1) + 1], a1);
        f = fmaxf(fmaf(sA[j + 2], v.z, sC[j + 2]), 0.f); a0 = fmaf(f, sW[2 * (j + 2)], a0); a1 = fmaf(f, sW[2 * (j + 2) + 1], a1);
        f = fmaxf(fmaf(sA[j + 3], v.w, sC[j + 3]), 0.f); a0 = fmaf(f, sW[2 * (j + 3)], a0); a1 = fmaf(f, sW[2 * (j + 3) + 1], a1);
    }
    out[2 * i]     = tanhf(a0);
    out[2 * i + 1] = tanhf(a1);
}

// ---------------- launch ----------------
extern "C" void kernel_launch(void* const* d_in, const int* in_sizes, int n_in,
                              void* d_out, int out_size) {
    const float* x    = (const float*)d_in[0];
    const int*   ei   = (const int*)d_in[1];
    const float* We   = (const float*)d_in[2];
    const float* be   = (const float*)d_in[3];
    const float* W1   = (const float*)d_in[4];
    const float* g1   = (const float*)d_in[6];
    const float* bt1  = (const float*)d_in[7];
    const float* W2   = (const float*)d_in[8];
    const float* g2   = (const float*)d_in[10];
    const float* bt2  = (const float*)d_in[11];
    const float* W3   = (const float*)d_in[12];
    const float* g3   = (const float*)d_in[14];
    const float* bt3  = (const float*)d_in[15];
    const float* Wf1  = (const float*)d_in[16];
    const float* gf   = (const float*)d_in[18];
    const float* btf  = (const float*)d_in[19];
    const float* Wf2  = (const float*)d_in[20];
    const float* bf2  = (const float*)d_in[21];
    float* out = (float*)d_out;
    // (b1/b2/b3/bf1 unused: uniform per-feature bias cancels inside BatchNorm)

    cudaFuncSetAttribute(k_mma_gemm, cudaFuncAttributeMaxDynamicSharedMemorySize, SMEM_MMA);

    const int nb_scan = (N_NODES + 1023) / 1024;   // 98
    const int GB = 592;

    // graph preprocessing: degree -> dinv, CSC build ; B-fragment prep
    k_zero_counts<<<(N_NODES + 255) / 256, 256>>>();
    k_count<<<(N_EDGES + 255) / 256, 256>>>(ei);
    k_dinv<<<(N_NODES + 255) / 256, 256>>>();
    k_scan_local<<<nb_scan, 1024>>>();
    k_scan_bsums<<<1, 128>>>(nb_scan);
    k_scan_add<<<nb_scan, 1024>>>();
    k_fill<<<(N_EDGES + 255) / 256, 256>>>(ei);
    k_prep_wfrag<<<48, 256>>>(W1, W2, W3);

    // block 1: encoder fused; h0 -> g
    k_mma_gemm<<<N_TILES, 256, SMEM_MMA>>>(x, We, be, 0, 0, 0, 1);
    k_aggregate<<<GB, 256>>>();
    k_bn_finalize<<<1, 128>>>(g1, bt1, HID);

    // block 2: bnrelu(block1) fused; h0 -> h1 -> g
    k_mma_gemm<<<N_TILES, 256, SMEM_MMA>>>(nullptr, nullptr, nullptr, 1, 0, 1, 0);
    k_aggregate<<<GB, 256>>>();
    k_bn_finalize<<<1, 128>>>(g2, bt2, HID);

    // block 3: bnrelu(block2) fused; h1 -> h0 -> g
    k_mma_gemm<<<N_TILES, 256, SMEM_MMA>>>(nullptr, nullptr, nullptr, 2, 1, 0, 0);
    k_aggregate<<<GB, 256>>>();
    k_bn_finalize<<<1, 128>>>(g3, bt3, HID);

    // head: bnrelu(block3) fused; h0 -> h3 (regs) -> ff in d_g, stats fused
    k_gemm32_fused<<<GB, 256>>>(Wf1, 0);
    k_bn_finalize<<<1, 128>>>(gf, btf, 32);
    k_out<<<(N_NODES + 127) / 128, 128>>>(Wf2, bf2, out);

    (void)in_sizes; (void)n_in; (void)out_size;
}

// round 10
// speedup vs baseline: 1.8631x; 1.1117x over previous
#include <cuda_runtime.h>
#include <cuda_fp16.h>
#include <math.h>
#include <stdint.h>

#define N_NODES 100000
#define N_EDGES 1600000
#define HID 128
#define EPS 1e-5f
#define N_TILES 782          // ceil(100000/128)
#define SM_STRIDE 136        // floats per staged row; 136 % 32 == 8 -> conflict-free frag LDS
#define SMEM_MMA (8 * 16 * SM_STRIDE * 4)   // 69632 B

// ---------------- scratch (device globals; referenced ONLY in device code) ----------------
__device__ float  d_h0[N_NODES * HID];
__device__ float  d_h1[N_NODES * HID];
__device__ __half d_g [N_NODES * HID];   // fp16 gather table: dinv-scaled h@W ; head reuses bytes as ff[N,32] fp32
__device__ float  d_agg[N_NODES * HID];
__device__ float  d_dinv[N_NODES];
__device__ int    d_cnt[N_NODES];
__device__ int    d_cursor[N_NODES];
__device__ int    d_rowptr[N_NODES + 1];
__device__ int    d_col[N_EDGES];
__device__ int    d_bsums[128];
__device__ double d_bnSum[HID];
__device__ double d_bnSqs[HID];
__device__ float  d_bnA[HID];
__device__ float  d_bnC[HID];
// B-fragment images: per (layer, kt, nt, lane): uint4 {bhi0, bhi1, blo0, blo1}
__device__ uint4  d_Wfrag[3 * 128 * 32];

// ---------------- helpers ----------------
__device__ __forceinline__ float* hbuf(int sel) { return sel == 0 ? d_h0 : d_h1; }

__device__ __forceinline__ uint32_t pack_bf16x2(float lo, float hi) {
    uint32_t d;
    asm("cvt.rn.bf16x2.f32 %0, %2, %1;" : "=r"(d) : "f"(lo), "f"(hi));
    return d;
}
__device__ __forceinline__ float bf_lo(uint32_t v) { return __uint_as_float(v << 16); }
__device__ __forceinline__ float bf_hi(uint32_t v) { return __uint_as_float(v & 0xffff0000u); }

// split float2 -> bf16x2 hi image + bf16x2 residual image
__device__ __forceinline__ void split2(float a, float b, uint32_t& hi, uint32_t& lo) {
    hi = pack_bf16x2(a, b);
    lo = pack_bf16x2(a - bf_lo(hi), b - bf_hi(hi));
}

__device__ __forceinline__ void mma_bf16(float c[4], uint32_t a0, uint32_t a1,
                                         uint32_t a2, uint32_t a3,
                                         uint32_t b0, uint32_t b1) {
    asm volatile(
        "mma.sync.aligned.m16n8k16.row.col.f32.bf16.bf16.f32 "
        "{%0,%1,%2,%3}, {%4,%5,%6,%7}, {%8,%9}, {%0,%1,%2,%3};"
        : "+f"(c[0]), "+f"(c[1]), "+f"(c[2]), "+f"(c[3])
        : "r"(a0), "r"(a1), "r"(a2), "r"(a3), "r"(b0), "r"(b1));
}

// accumulate 4 halves (as uint2) into float4
__device__ __forceinline__ void addh4(float4& a, uint2 v) {
    float2 f0 = __half22float2(*reinterpret_cast<const __half2*>(&v.x));
    float2 f1 = __half22float2(*reinterpret_cast<const __half2*>(&v.y));
    a.x += f0.x; a.y += f0.y; a.z += f1.x; a.w += f1.y;
}

// ---------------- setup kernels ----------------
__global__ void k_zero_counts() {
    int i = blockIdx.x * blockDim.x + threadIdx.x;
    if (i < N_NODES) { d_cnt[i] = 0; d_cursor[i] = 0; }
}
__global__ void k_count(const int* __restrict__ ei) {
    int e = blockIdx.x * blockDim.x + threadIdx.x;
    if (e < N_EDGES) atomicAdd(&d_cnt[ei[N_EDGES + e]], 1);
}
__global__ void k_dinv() {
    int i = blockIdx.x * blockDim.x + threadIdx.x;
    if (i < N_NODES) d_dinv[i] = rsqrtf((float)d_cnt[i] + 1.0f);
}
__global__ void k_scan_local() {
    __shared__ int s[1024];
    int tid = threadIdx.x;
    int idx = blockIdx.x * 1024 + tid;
    int v = (idx < N_NODES) ? d_cnt[idx] : 0;
    s[tid] = v;
    __syncthreads();
    for (int off = 1; off < 1024; off <<= 1) {
        int t = (tid >= off) ? s[tid - off] : 0;
        __syncthreads();
        s[tid] += t;
        __syncthreads();
    }
    if (idx < N_NODES) d_rowptr[idx] = s[tid] - v;   // exclusive
    if (tid == 1023) d_bsums[blockIdx.x] = s[1023];
}
__global__ void k_scan_bsums(int nb) {
    __shared__ int sb[128];
    int t = threadIdx.x;
    sb[t] = (t < nb) ? d_bsums[t] : 0;
    __syncthreads();
    if (t == 0) {
        int run = 0;
        for (int i = 0; i < nb; i++) { int x = sb[i]; sb[i] = run; run += x; }
        d_rowptr[N_NODES] = run;
    }
    __syncthreads();
    if (t < nb) d_bsums[t] = sb[t];
}
__global__ void k_scan_add() {
    int idx = blockIdx.x * 1024 + threadIdx.x;
    if (idx < N_NODES) d_rowptr[idx] += d_bsums[blockIdx.x];
}
__global__ void k_fill(const int* __restrict__ ei) {
    int e = blockIdx.x * blockDim.x + threadIdx.x;
    if (e < N_EDGES) {
        int s = ei[e];
        int d = ei[N_EDGES + e];
        int pos = d_rowptr[d] + atomicAdd(&d_cursor[d], 1);
        d_col[pos] = s;
    }
}

// ---------------- W prep: build per-(kt,nt,lane) B fragments, bf16 hi/lo ----------------
__global__ void k_prep_wfrag(const float* __restrict__ W1,
                             const float* __restrict__ W2,
                             const float* __restrict__ W3) {
    int idx = blockIdx.x * blockDim.x + threadIdx.x;
    if (idx >= 3 * 8 * 16 * 32) return;
    int lane = idx & 31;
    int nt = (idx >> 5) & 15;
    int kt = (idx >> 9) & 7;
    int L  = idx >> 12;
    const float* W = (L == 0) ? W1 : (L == 1) ? W2 : W3;
    int g = lane >> 2, t = lane & 3;
    int n = nt * 8 + g;
    int k0 = kt * 16 + 2 * t;
    int k1 = kt * 16 + 2 * t + 8;
    uint32_t h0, l0, h1, l1;
    split2(W[k0 * 128 + n], W[(k0 + 1) * 128 + n], h0, l0);
    split2(W[k1 * 128 + n], W[(k1 + 1) * 128 + n], h1, l1);
    uint4 v; v.x = h0; v.y = h1; v.z = l0; v.w = l1;
    d_Wfrag[(L * 128 + kt * 16 + nt) * 32 + lane] = v;
}

// ---------------- tensor GEMM: d_g(fp16) = dinv * (h_new @ W_layer) ----------------
__global__ void __launch_bounds__(256, 2) k_mma_gemm(
    const float* __restrict__ x, const float* __restrict__ We,
    const float* __restrict__ be,
    int layer, int hin_sel, int hout_sel, int first) {
    extern __shared__ float smf[];
    const int lane = threadIdx.x & 31;
    const int wid = threadIdx.x >> 5;
    const int tile = blockIdx.x;
    float* sw = smf + wid * 16 * SM_STRIDE;
    const int rbase = tile * 128 + wid * 16;

    if (first && blockIdx.x == 0 && threadIdx.x < HID) {
        d_bnSum[threadIdx.x] = 0.0;
        d_bnSqs[threadIdx.x] = 0.0;
    }

    // ---- phase 1: h_new for this warp's 16 rows ----
    if (first) {
        float4 w0 = __ldg(&((const float4*)We)[lane]);
        float4 w1 = __ldg(&((const float4*)We)[32 + lane]);
        float4 b  = __ldg(&((const float4*)be)[lane]);
        float4* H04 = reinterpret_cast<float4*>(d_h0);
        #pragma unroll 4
        for (int r = 0; r < 16; r++) {
            int row = rbase + r;
            int rs = (row < N_NODES) ? row : N_NODES - 1;
            float x0 = __ldg(&x[2 * rs]), x1 = __ldg(&x[2 * rs + 1]);
            float4 h;
            h.x = fmaxf(fmaf(x0, w0.x, fmaf(x1, w1.x, b.x)), 0.f);
            h.y = fmaxf(fmaf(x0, w0.y, fmaf(x1, w1.y, b.y)), 0.f);
            h.z = fmaxf(fmaf(x0, w0.z, fmaf(x1, w1.z, b.z)), 0.f);
            h.w = fmaxf(fmaf(x0, w0.w, fmaf(x1, w1.w, b.w)), 0.f);
            if (row < N_NODES) H04[(size_t)row * 32 + lane] = h;
            *reinterpret_cast<float4*>(sw + r * SM_STRIDE + 4 * lane) = h;
        }
    } else {
        float4 ba = ((const float4*)d_bnA)[lane];
        float4 bc = ((const float4*)d_bnC)[lane];
        const float4* A4 = reinterpret_cast<const float4*>(d_agg);
        const float4* HI4 = reinterpret_cast<const float4*>(hbuf(hin_sel));
        float4* HO4 = reinterpret_cast<float4*>(hbuf(hout_sel));
        #pragma unroll 4
        for (int r = 0; r < 16; r++) {
            int row = rbase + r;
            int rs = (row < N_NODES) ? row : N_NODES - 1;
            float4 v = A4[(size_t)rs * 32 + lane];
            float4 ho = HI4[(size_t)rs * 32 + lane];
            float4 h;
            h.x = fmaxf(fmaf(ba.x, v.x, bc.x), 0.f) + ho.x;
            h.y = fmaxf(fmaf(ba.y, v.y, bc.y), 0.f) + ho.y;
            h.z = fmaxf(fmaf(ba.z, v.z, bc.z), 0.f) + ho.z;
            h.w = fmaxf(fmaf(ba.w, v.w, bc.w), 0.f) + ho.w;
            if (row < N_NODES) HO4[(size_t)row * 32 + lane] = h;
            *reinterpret_cast<float4*>(sw + r * SM_STRIDE + 4 * lane) = h;
        }
    }
    __syncwarp();

    // ---- phase 2: A fragments (split bf16), 8 k-tiles ----
    const int g = lane >> 2, t = lane & 3;
    const float* r0p = sw + g * SM_STRIDE;
    const float* r1p = sw + (g + 8) * SM_STRIDE;
    uint32_t ah[32], al[32];
    #pragma unroll
    for (int kt = 0; kt < 8; kt++) {
        float2 p0 = *reinterpret_cast<const float2*>(r0p + 16 * kt + 2 * t);
        float2 p1 = *reinterpret_cast<const float2*>(r1p + 16 * kt + 2 * t);
        float2 p2 = *reinterpret_cast<const float2*>(r0p + 16 * kt + 2 * t + 8);
        float2 p3 = *reinterpret_cast<const float2*>(r1p + 16 * kt + 2 * t + 8);
        split2(p0.x, p0.y, ah[4 * kt + 0], al[4 * kt + 0]);
        split2(p1.x, p1.y, ah[4 * kt + 1], al[4 * kt + 1]);
        split2(p2.x, p2.y, ah[4 * kt + 2], al[4 * kt + 2]);
        split2(p3.x, p3.y, ah[4 * kt + 3], al[4 * kt + 3]);
    }

    // ---- phase 3: mma over 16 n-tiles (2 at a time), 3-pass split bf16; fp16 epilogue ----
    const uint4* Wf = &d_Wfrag[layer * 128 * 32];
    int row0 = rbase + g, row1 = rbase + g + 8;
    float dv0 = d_dinv[(row0 < N_NODES) ? row0 : 0];
    float dv1 = d_dinv[(row1 < N_NODES) ? row1 : 0];

    #pragma unroll
    for (int ntp = 0; ntp < 8; ntp++) {
        float c0[4] = {0.f, 0.f, 0.f, 0.f};
        float c1[4] = {0.f, 0.f, 0.f, 0.f};
        #pragma unroll
        for (int kt = 0; kt < 8; kt++) {
            uint4 B0 = __ldg(&Wf[(kt * 16 + 2 * ntp) * 32 + lane]);
            uint4 B1 = __ldg(&Wf[(kt * 16 + 2 * ntp + 1) * 32 + lane]);
            uint32_t a0 = ah[4 * kt], a1 = ah[4 * kt + 1], a2 = ah[4 * kt + 2], a3 = ah[4 * kt + 3];
            uint32_t l0 = al[4 * kt], l1 = al[4 * kt + 1], l2 = al[4 * kt + 2], l3 = al[4 * kt + 3];
            mma_bf16(c0, a0, a1, a2, a3, B0.x, B0.y);   // Ah * Bh
            mma_bf16(c0, l0, l1, l2, l3, B0.x, B0.y);   // Al * Bh
            mma_bf16(c0, a0, a1, a2, a3, B0.z, B0.w);   // Ah * Bl
            mma_bf16(c1, a0, a1, a2, a3, B1.x, B1.y);
            mma_bf16(c1, l0, l1, l2, l3, B1.x, B1.y);
            mma_bf16(c1, a0, a1, a2, a3, B1.z, B1.w);
        }
        int col0 = (2 * ntp) * 8 + 2 * t;
        int col1 = (2 * ntp + 1) * 8 + 2 * t;
        if (row0 < N_NODES) {
            *reinterpret_cast<__half2*>(d_g + (size_t)row0 * 128 + col0) =
                __floats2half2_rn(c0[0] * dv0, c0[1] * dv0);
            *reinterpret_cast<__half2*>(d_g + (size_t)row0 * 128 + col1) =
                __floats2half2_rn(c1[0] * dv0, c1[1] * dv0);
        }
        if (row1 < N_NODES) {
            *reinterpret_cast<__half2*>(d_g + (size_t)row1 * 128 + col0) =
                __floats2half2_rn(c0[2] * dv1, c0[3] * dv1);
            *reinterpret_cast<__half2*>(d_g + (size_t)row1 * 128 + col1) =
                __floats2half2_rn(c1[2] * dv1, c1[3] * dv1);
        }
    }
}

// ---------------- aggregation: agg[i] = dinv[i]*(sum_in g[src] + g[i]); BN partials ---
// d_g is fp16: lane reads 4 halves (uint2, 8B) per row -> half the L2 gather bytes
__global__ void k_aggregate() {
    __shared__ float sS[HID];
    __shared__ float sQ[HID];
    if (threadIdx.x < HID) { sS[threadIdx.x] = 0.f; sQ[threadIdx.x] = 0.f; }
    __syncthreads();

    const int lane = threadIdx.x & 31;
    const int gwid = (blockIdx.x * blockDim.x + threadIdx.x) >> 5;
    const int nwarps = (gridDim.x * blockDim.x) >> 5;
    const uint2* g2 = reinterpret_cast<const uint2*>(d_g);
    float4* agg4 = reinterpret_cast<float4*>(d_agg);

    float4 lsum = make_float4(0.f, 0.f, 0.f, 0.f);
    float4 lsq  = make_float4(0.f, 0.f, 0.f, 0.f);

    for (int i = gwid; i < N_NODES; i += nwarps) {
        float4 acc = make_float4(0.f, 0.f, 0.f, 0.f);
        addh4(acc, __ldg(&g2[(size_t)i * 32 + lane]));   // self loop
        int e0 = d_rowptr[i], e1 = d_rowptr[i + 1];
        int e = e0;
        for (; e + 4 <= e1; e += 4) {                    // unroll x4 for gather MLP
            int s0 = __ldg(&d_col[e]);
            int s1 = __ldg(&d_col[e + 1]);
            int s2 = __ldg(&d_col[e + 2]);
            int s3 = __ldg(&d_col[e + 3]);
            uint2 v0 = __ldg(&g2[(size_t)s0 * 32 + lane]);
            uint2 v1 = __ldg(&g2[(size_t)s1 * 32 + lane]);
            uint2 v2 = __ldg(&g2[(size_t)s2 * 32 + lane]);
            uint2 v3 = __ldg(&g2[(size_t)s3 * 32 + lane]);
            addh4(acc, v0); addh4(acc, v1); addh4(acc, v2); addh4(acc, v3);
        }
        for (; e < e1; e++) {
            int s0 = __ldg(&d_col[e]);
            addh4(acc, __ldg(&g2[(size_t)s0 * 32 + lane]));
        }
        float dv = d_dinv[i];
        acc.x *= dv; acc.y *= dv; acc.z *= dv; acc.w *= dv;
        agg4[(size_t)i * 32 + lane] = acc;
        lsum.x += acc.x; lsum.y += acc.y; lsum.z += acc.z; lsum.w += acc.w;
        lsq.x = fmaf(acc.x, acc.x, lsq.x);
        lsq.y = fmaf(acc.y, acc.y, lsq.y);
        lsq.z = fmaf(acc.z, acc.z, lsq.z);
        lsq.w = fmaf(acc.w, acc.w, lsq.w);
    }
    int f = 4 * lane;
    atomicAdd(&sS[f + 0], lsum.x); atomicAdd(&sS[f + 1], lsum.y);
    atomicAdd(&sS[f + 2], lsum.z); atomicAdd(&sS[f + 3], lsum.w);
    atomicAdd(&sQ[f + 0], lsq.x);  atomicAdd(&sQ[f + 1], lsq.y);
    atomicAdd(&sQ[f + 2], lsq.z);  atomicAdd(&sQ[f + 3], lsq.w);
    __syncthreads();
    if (threadIdx.x < HID) {
        atomicAdd(&d_bnSum[threadIdx.x], (double)sS[threadIdx.x]);
        atomicAdd(&d_bnSqs[threadIdx.x], (double)sQ[threadIdx.x]);
    }
}

// ---------------- BN coeffs: a = gamma*rsqrt(var+eps), c = beta - mean*a; zero accs ----
__global__ void k_bn_finalize(const float* __restrict__ gamma,
                              const float* __restrict__ beta, int nfeat) {
    int t = threadIdx.x;
    if (t < nfeat) {
        double mean = d_bnSum[t] / (double)N_NODES;
        double var  = d_bnSqs[t] / (double)N_NODES - mean * mean;
        float a = gamma[t] * rsqrtf((float)var + EPS);
        d_bnA[t] = a;
        d_bnC[t] = beta[t] - (float)mean * a;
        d_bnSum[t] = 0.0;       // ready for next layer's stats
        d_bnSqs[t] = 0.0;
    }
}

// ---------------- head gemm: h3 = relu(a*agg+c)+h2 inline; ff = h3@Wf1; BN stats ------
// ff written as fp32 into d_g's storage (disjoint in time from fp16 use)
__global__ void k_gemm32_fused(const float* __restrict__ W, int hin_sel) {
    __shared__ float sW[HID * 32];
    __shared__ float sS[32];
    __shared__ float sQ[32];
    for (int i = threadIdx.x; i < HID * 32; i += blockDim.x) sW[i] = W[i];
    if (threadIdx.x < 32) { sS[threadIdx.x] = 0.f; sQ[threadIdx.x] = 0.f; }
    __syncthreads();
    const int lane = threadIdx.x & 31;
    const int gwid = (blockIdx.x * blockDim.x + threadIdx.x) >> 5;
    const int nwarps = (gridDim.x * blockDim.x) >> 5;
    const float4* A4 = reinterpret_cast<const float4*>(d_agg);
    const float4* HI4 = reinterpret_cast<const float4*>(hbuf(hin_sel));
    float* ff = reinterpret_cast<float*>(d_g);
    float4 ba = ((const float4*)d_bnA)[lane];
    float4 bc = ((const float4*)d_bnC)[lane];
    float s = 0.f, q = 0.f;

    for (int i = gwid; i < N_NODES; i += nwarps) {
        float4 v = A4[(size_t)i * 32 + lane];
        float4 ho = HI4[(size_t)i * 32 + lane];
        float4 h;
        h.x = fmaxf(fmaf(ba.x, v.x, bc.x), 0.f) + ho.x;
        h.y = fmaxf(fmaf(ba.y, v.y, bc.y), 0.f) + ho.y;
        h.z = fmaxf(fmaf(ba.z, v.z, bc.z), 0.f) + ho.z;
        h.w = fmaxf(fmaf(ba.w, v.w, bc.w), 0.f) + ho.w;
        float acc = 0.f;
        #pragma unroll 8
        for (int p = 0; p < 32; p++) {
            float sx = __shfl_sync(0xffffffffu, h.x, p);
            float sy = __shfl_sync(0xffffffffu, h.y, p);
            float sz = __shfl_sync(0xffffffffu, h.z, p);
            float sw = __shfl_sync(0xffffffffu, h.w, p);
            acc = fmaf(sx, sW[(4 * p + 0) * 32 + lane], acc);
            acc = fmaf(sy, sW[(4 * p + 1) * 32 + lane], acc);
            acc = fmaf(sz, sW[(4 * p + 2) * 32 + lane], acc);
            acc = fmaf(sw, sW[(4 * p + 3) * 32 + lane], acc);
        }
        ff[(size_t)i * 32 + lane] = acc;
        s += acc;
        q = fmaf(acc, acc, q);
    }
    atomicAdd(&sS[lane], s);
    atomicAdd(&sQ[lane], q);
    __syncthreads();
    if (threadIdx.x < 32) {
        atomicAdd(&d_bnSum[threadIdx.x], (double)sS[threadIdx.x]);
        atomicAdd(&d_bnSqs[threadIdx.x], (double)sQ[threadIdx.x]);
    }
}

// ---------------- out = tanh(relu(a*ff+c) @ Wf2 + bf2) ----------------
__global__ void k_out(const float* __restrict__ Wf2,
                      const float* __restrict__ bf2,
                      float* __restrict__ out) {
    __shared__ float sA[32], sC[32], sW[64], sB[2];
    int t = threadIdx.x;
    if (t < 32) { sA[t] = d_bnA[t]; sC[t] = d_bnC[t]; }
    if (t < 64) sW[t] = Wf2[t];
    if (t < 2) sB[t] = bf2[t];
    __syncthreads();
    int i = blockIdx.x * blockDim.x + t;
    if (i >= N_NODES) return;
    float a0 = sB[0], a1 = sB[1];
    const float4* f4 = reinterpret_cast<const float4*>(reinterpret_cast<const float*>(d_g) + (size_t)i * 32);
    #pragma unroll
    for (int j4 = 0; j4 < 8; j4++) {
        float4 v = f4[j4];
        int j = j4 * 4;
        float f;
        f = fmaxf(fmaf(sA[j + 0], v.x, sC[j + 0]), 0.f); a0 = fmaf(f, sW[2 * (j + 0)], a0); a1 = fmaf(f, sW[2 * (j + 0) + 1], a1);
        f = fmaxf(fmaf(sA[j + 1], v.y, sC[j + 1]), 0.f); a0 = fmaf(f, sW[2 * (j + 1)], a0); a1 = fmaf(f, sW[2 * (j + 1) + 1], a1);
        f = fmaxf(fmaf(sA[j + 2], v.z, sC[j + 2]), 0.f); a0 = fmaf(f, sW[2 * (j + 2)], a0); a1 = fmaf(f, sW[2 * (j + 2) + 1], a1);
        f = fmaxf(fmaf(sA[j + 3], v.w, sC[j + 3]), 0.f); a0 = fmaf(f, sW[2 * (j + 3)], a0); a1 = fmaf(f, sW[2 * (j + 3) + 1], a1);
    }
    out[2 * i]     = tanhf(a0);
    out[2 * i + 1] = tanhf(a1);
}

// ---------------- launch ----------------
extern "C" void kernel_launch(void* const* d_in, const int* in_sizes, int n_in,
                              void* d_out, int out_size) {
    const float* x    = (const float*)d_in[0];
    const int*   ei   = (const int*)d_in[1];
    const float* We   = (const float*)d_in[2];
    const float* be   = (const float*)d_in[3];
    const float* W1   = (const float*)d_in[4];
    const float* g1   = (const float*)d_in[6];
    const float* bt1  = (const float*)d_in[7];
    const float* W2   = (const float*)d_in[8];
    const float* g2   = (const float*)d_in[10];
    const float* bt2  = (const float*)d_in[11];
    const float* W3   = (const float*)d_in[12];
    const float* g3   = (const float*)d_in[14];
    const float* bt3  = (const float*)d_in[15];
    const float* Wf1  = (const float*)d_in[16];
    const float* gf   = (const float*)d_in[18];
    const float* btf  = (const float*)d_in[19];
    const float* Wf2  = (const float*)d_in[20];
    const float* bf2  = (const float*)d_in[21];
    float* out = (float*)d_out;
    // (b1/b2/b3/bf1 unused: uniform per-feature bias cancels inside BatchNorm)

    cudaFuncSetAttribute(k_mma_gemm, cudaFuncAttributeMaxDynamicSharedMemorySize, SMEM_MMA);

    const int nb_scan = (N_NODES + 1023) / 1024;   // 98
    const int GB = 592;

    // graph preprocessing: degree -> dinv, CSC build ; B-fragment prep
    k_zero_counts<<<(N_NODES + 255) / 256, 256>>>();
    k_count<<<(N_EDGES + 255) / 256, 256>>>(ei);
    k_dinv<<<(N_NODES + 255) / 256, 256>>>();
    k_scan_local<<<nb_scan, 1024>>>();
    k_scan_bsums<<<1, 128>>>(nb_scan);
    k_scan_add<<<nb_scan, 1024>>>();
    k_fill<<<(N_EDGES + 255) / 256, 256>>>(ei);
    k_prep_wfrag<<<48, 256>>>(W1, W2, W3);

    // block 1: encoder fused; h0 -> g
    k_mma_gemm<<<N_TILES, 256, SMEM_MMA>>>(x, We, be, 0, 0, 0, 1);
    k_aggregate<<<GB, 256>>>();
    k_bn_finalize<<<1, 128>>>(g1, bt1, HID);

    // block 2: bnrelu(block1) fused; h0 -> h1 -> g
    k_mma_gemm<<<N_TILES, 256, SMEM_MMA>>>(nullptr, nullptr, nullptr, 1, 0, 1, 0);
    k_aggregate<<<GB, 256>>>();
    k_bn_finalize<<<1, 128>>>(g2, bt2, HID);

    // block 3: bnrelu(block2) fused; h1 -> h0 -> g
    k_mma_gemm<<<N_TILES, 256, SMEM_MMA>>>(nullptr, nullptr, nullptr, 2, 1, 0, 0);
    k_aggregate<<<GB, 256>>>();
    k_bn_finalize<<<1, 128>>>(g3, bt3, HID);

    // head: bnrelu(block3) fused; h0 -> h3 (regs) -> ff, stats fused
    k_gemm32_fused<<<GB, 256>>>(Wf1, 0);
    k_bn_finalize<<<1, 128>>>(gf, btf, 32);
    k_out<<<(N_NODES + 127) / 128, 128>>>(Wf2, bf2, out);

    (void)in_sizes; (void)n_in; (void)out_size;
}